// round 8
// baseline (speedup 1.0000x reference)
#include <cuda_runtime.h>
#include <cuda_bf16.h>
#include <math.h>

#define N_NODES_MAX 100000
#define D_IN        256
#define H1          16
#define H2          32
#define KT          16       // k-tile staged per iteration
#define G_THREADS   256
#define G_ROWS      512      // rows per block (2 per thread)
#define STRIDE      20       // floats per tile row: 20%32=20=4*5 -> LDS.128 conflict-free

#define FMA2(d, a, b) \
    asm("fma.rn.f32x2 %0, %1, %2, %0;" : "+l"(d) : "l"(a), "l"(b))

// Scratch (device globals — BSS zero-init; every call leaves them zeroed again,
// so the kernel is deterministic across graph replays).
__device__ __align__(256) float g_y[N_NODES_MAX * H1];   // x @ W1
__device__ __align__(256) float g_a[N_NODES_MAX * H1];   // spmm accumulator (pre-relu)
__device__ __align__(256) float g_s[N_NODES_MAX];        // s[j] = sum_{e: col==j} val[e]
__device__ __align__(256) float g_t[H1];                 // t = sum_i s[i]*relu(a[i])
__device__ unsigned g_ticket;                            // last-block ticket

// ---------------------------------------------------------------------------
// y = x @ W1   (N x 256) @ (256 x 16)
// 512 rows/block (2 per thread), row-major stride-20 tile: staging STS.128
// (deg-2 max) and compute LDS.128 (conflict-free, 4 k per load). W broadcast
// as ulonglong2 -> fma.rn.f32x2.
// ---------------------------------------------------------------------------
__global__ void __launch_bounds__(G_THREADS, 4)
gemm1_kernel(const float* __restrict__ x, const float* __restrict__ W1, int n) {
    extern __shared__ float smem[];
    float* sW = smem;                    // [D_IN*H1] = 4096 floats (16 KB)
    float* sx = smem + D_IN * H1;        // [G_ROWS][STRIDE] row-major (40 KB)

    int tid = threadIdx.x;
#pragma unroll
    for (int i = 0; i < 4; i++)
        reinterpret_cast<float4*>(sW)[tid + i * G_THREADS] =
            reinterpret_cast<const float4*>(W1)[tid + i * G_THREADS];

    int row0 = blockIdx.x * G_ROWS;
    int rA = row0 + tid;
    int rB = row0 + tid + G_THREADS;

    unsigned long long accA[8], accB[8];   // f32x2 pairs: features (0,1)..(14,15)
#pragma unroll
    for (int j = 0; j < 8; j++) { accA[j] = 0ull; accB[j] = 0ull; }

    for (int kt = 0; kt < D_IN; kt += KT) {
        __syncthreads();   // protect sx (prev-iter reads / sW load on iter 0)
        // Stage: 512 rows x 16 k = 2048 float4; 8 per thread; r=idx>>2, kv=idx&3.
#pragma unroll
        for (int i = 0; i < 8; i++) {
            int idx = tid + i * G_THREADS;
            int r = idx >> 2, kv = idx & 3;
            if (row0 + r < n) {
                float4 v = __ldg(reinterpret_cast<const float4*>(
                    x + (size_t)(row0 + r) * D_IN + kt + kv * 4));
                *reinterpret_cast<float4*>(sx + r * STRIDE + kv * 4) = v;
            }
        }
        __syncthreads();
#pragma unroll
        for (int kk4 = 0; kk4 < KT / 4; kk4++) {
            float4 xa = *reinterpret_cast<const float4*>(sx + tid * STRIDE + kk4 * 4);
            float4 xb = *reinterpret_cast<const float4*>(
                sx + (tid + G_THREADS) * STRIDE + kk4 * 4);
#pragma unroll
            for (int j = 0; j < 4; j++) {
                float fa = (j == 0) ? xa.x : (j == 1) ? xa.y : (j == 2) ? xa.z : xa.w;
                float fb = (j == 0) ? xb.x : (j == 1) ? xb.y : (j == 2) ? xb.z : xb.w;
                unsigned long long xa2, xb2;
                asm("mov.b64 %0, {%1, %1};" : "=l"(xa2) : "f"(fa));
                asm("mov.b64 %0, {%1, %1};" : "=l"(xb2) : "f"(fb));
                const ulonglong2* wp = reinterpret_cast<const ulonglong2*>(
                    sW + (kt + kk4 * 4 + j) * H1);
                ulonglong2 w01 = wp[0], w23 = wp[1], w45 = wp[2], w67 = wp[3];
                FMA2(accA[0], xa2, w01.x); FMA2(accA[1], xa2, w01.y);
                FMA2(accA[2], xa2, w23.x); FMA2(accA[3], xa2, w23.y);
                FMA2(accA[4], xa2, w45.x); FMA2(accA[5], xa2, w45.y);
                FMA2(accA[6], xa2, w67.x); FMA2(accA[7], xa2, w67.y);
                FMA2(accB[0], xb2, w01.x); FMA2(accB[1], xb2, w01.y);
                FMA2(accB[2], xb2, w23.x); FMA2(accB[3], xb2, w23.y);
                FMA2(accB[4], xb2, w45.x); FMA2(accB[5], xb2, w45.y);
                FMA2(accB[6], xb2, w67.x); FMA2(accB[7], xb2, w67.y);
            }
        }
    }
    if (rA < n) {
        ulonglong2* yr = reinterpret_cast<ulonglong2*>(g_y + (size_t)rA * H1);
        yr[0] = make_ulonglong2(accA[0], accA[1]);
        yr[1] = make_ulonglong2(accA[2], accA[3]);
        yr[2] = make_ulonglong2(accA[4], accA[5]);
        yr[3] = make_ulonglong2(accA[6], accA[7]);
    }
    if (rB < n) {
        ulonglong2* yr = reinterpret_cast<ulonglong2*>(g_y + (size_t)rB * H1);
        yr[0] = make_ulonglong2(accB[0], accB[1]);
        yr[1] = make_ulonglong2(accB[2], accB[3]);
        yr[2] = make_ulonglong2(accB[4], accB[5]);
        yr[3] = make_ulonglong2(accB[6], accB[7]);
    }
}

// ---------------------------------------------------------------------------
// Edge pass, one thread per edge:
//   a[r][0:16] += v * y[c][0:16]   (4x red.global.add.v4.f32)
//   s[c] += v
// ---------------------------------------------------------------------------
__global__ void edge_kernel(const int* __restrict__ rows,
                            const int* __restrict__ cols,
                            const float* __restrict__ vals, int e_count) {
    int e = blockIdx.x * blockDim.x + threadIdx.x;
    if (e >= e_count) return;

    int r = __ldg(rows + e);
    int c = __ldg(cols + e);
    float v = __ldg(vals + e);

    const float4* yp = reinterpret_cast<const float4*>(g_y + (size_t)c * H1);
    float4 y0 = __ldg(yp), y1 = __ldg(yp + 1), y2 = __ldg(yp + 2), y3 = __ldg(yp + 3);
    float* dst = g_a + (size_t)r * H1;
    asm volatile("red.global.add.v4.f32 [%0], {%1, %2, %3, %4};"
                 :: "l"(dst), "f"(v * y0.x), "f"(v * y0.y), "f"(v * y0.z), "f"(v * y0.w) : "memory");
    asm volatile("red.global.add.v4.f32 [%0], {%1, %2, %3, %4};"
                 :: "l"(dst + 4), "f"(v * y1.x), "f"(v * y1.y), "f"(v * y1.z), "f"(v * y1.w) : "memory");
    asm volatile("red.global.add.v4.f32 [%0], {%1, %2, %3, %4};"
                 :: "l"(dst + 8), "f"(v * y2.x), "f"(v * y2.y), "f"(v * y2.z), "f"(v * y2.w) : "memory");
    asm volatile("red.global.add.v4.f32 [%0], {%1, %2, %3, %4};"
                 :: "l"(dst + 12), "f"(v * y3.x), "f"(v * y3.y), "f"(v * y3.z), "f"(v * y3.w) : "memory");
    atomicAdd(&g_s[c], v);
}

// ---------------------------------------------------------------------------
// t[f] = sum_i s[i] * relu(a[i][f]); self-cleans g_a/g_s; last block computes
// the final output and cleans g_t/g_ticket.
// ---------------------------------------------------------------------------
__global__ void reduce_final_kernel(int n,
                                    const float* __restrict__ W2,
                                    const float* __restrict__ w_out,
                                    const float* __restrict__ b_out,
                                    float* __restrict__ out) {
    __shared__ float4 red[256];
    __shared__ bool is_last;
    int tid = threadIdx.x;
    int g = tid & 3;  // feature group: covers features [4g, 4g+4)
    const float4 z4 = {0.f, 0.f, 0.f, 0.f};
    float4 acc = z4;
    int total = n * 4;
    int stride = gridDim.x * blockDim.x;
    for (int idx = blockIdx.x * blockDim.x + tid; idx < total; idx += stride) {
        int i = idx >> 2;
        float4* ap = reinterpret_cast<float4*>(g_a + (size_t)i * H1 + g * 4);
        float4 av = *ap;
        float s = 0.0f;
        if (g == 0) { s = g_s[i]; g_s[i] = 0.0f; }   // sole reader of g_s[i]
        s = __shfl_sync(0xffffffffu, s, (tid & 31) & ~3);
        *ap = z4;                                     // self-clean g_a
        acc.x += s * fmaxf(av.x, 0.f);
        acc.y += s * fmaxf(av.y, 0.f);
        acc.z += s * fmaxf(av.z, 0.f);
        acc.w += s * fmaxf(av.w, 0.f);
    }
    red[tid] = acc;
    __syncthreads();
#pragma unroll
    for (int off = 128; off >= 4; off >>= 1) {
        if (tid < off) {
            float4 o = red[tid + off];
            red[tid].x += o.x; red[tid].y += o.y; red[tid].z += o.z; red[tid].w += o.w;
        }
        __syncthreads();
    }
    if (tid < 4) {
        float4 r4 = red[tid];
        float* dst = g_t + tid * 4;
        asm volatile("red.global.add.v4.f32 [%0], {%1, %2, %3, %4};"
                     :: "l"(dst), "f"(r4.x), "f"(r4.y), "f"(r4.z), "f"(r4.w) : "memory");
    }
    __threadfence();
    if (tid == 0) {
        unsigned done = atomicAdd(&g_ticket, 1u);
        is_last = (done == gridDim.x - 1);
    }
    __syncthreads();
    if (is_last) {
        __threadfence();  // pair with producers' fences
        float z = 0.0f;
        if (tid < H2) {
#pragma unroll
            for (int fi = 0; fi < H1; fi++) z += g_t[fi] * W2[fi * H2 + tid];
        }
        __syncthreads();
        if (tid < H1) g_t[tid] = 0.0f;   // self-clean g_t
        if (tid == 0) g_ticket = 0u;     // self-clean ticket
        if (tid < H2) {
            float p = z * w_out[tid];
#pragma unroll
            for (int o = 16; o > 0; o >>= 1) p += __shfl_xor_sync(0xffffffffu, p, o);
            if (tid == 0) out[0] = 1.0f / (1.0f + expf(-(p + b_out[0])));
        }
    }
}

// ---------------------------------------------------------------------------
extern "C" void kernel_launch(void* const* d_in, const int* in_sizes, int n_in,
                              void* d_out, int out_size) {
    const float* x     = (const float*)d_in[0];
    const float* vals  = (const float*)d_in[1];
    const float* W1    = (const float*)d_in[2];
    const float* W2    = (const float*)d_in[3];
    const float* w_out = (const float*)d_in[4];
    const float* b_out = (const float*)d_in[5];
    const int*   rows  = (const int*)d_in[6];
    const int*   cols  = (const int*)d_in[7];

    int n = in_sizes[0] / D_IN;   // 100000
    int e = in_sizes[1];          // 3200000

    int smem_bytes = (D_IN * H1 + G_ROWS * STRIDE) * sizeof(float);  // 57344 B
    cudaFuncSetAttribute(gemm1_kernel,
                         cudaFuncAttributeMaxDynamicSharedMemorySize, smem_bytes);

    gemm1_kernel<<<(n + G_ROWS - 1) / G_ROWS, G_THREADS, smem_bytes>>>(x, W1, n);
    edge_kernel<<<(e + 255) / 256, 256>>>(rows, cols, vals, e);
    reduce_final_kernel<<<1024, 256>>>(n, W2, w_out, b_out, (float*)d_out);
}

// round 10
// speedup vs baseline: 1.4510x; 1.4510x over previous
#include <cuda_runtime.h>
#include <cuda_bf16.h>
#include <math.h>

#define N_NODES_MAX 100000
#define D_IN        256
#define H1          16
#define H2          32
#define KT          32     // k-tile for gemm1
#define G_THREADS   256    // threads per gemm1 block (1 row per thread)

#define FMA2(d, a, b) \
    asm("fma.rn.f32x2 %0, %1, %2, %0;" : "+l"(d) : "l"(a), "l"(b))

// Scratch (device globals — BSS zero-init; every call leaves them zeroed again,
// so the kernel is deterministic across graph replays).
__device__ __align__(256) float g_y[N_NODES_MAX * H1];   // x @ W1
__device__ __align__(256) float g_a[N_NODES_MAX * H1];   // spmm accumulator (pre-relu)
__device__ __align__(256) float g_s[N_NODES_MAX];        // s[j] = sum_{e: col==j} val[e]
__device__ __align__(256) float g_t[H1];                 // t = sum_i s[i]*relu(a[i])
__device__ unsigned g_ticket;                            // last-block ticket

// ---------------------------------------------------------------------------
// y = x @ W1   (N x 256) @ (256 x 16)   [R6 config — best known]
// 256 thr, 1 row/thread, coalesced LDG -> transposed pad-257 tile
// (conflict-free both phases), packed fma.rn.f32x2 + 64-bit W loads.
// ---------------------------------------------------------------------------
__global__ void gemm1_kernel(const float* __restrict__ x,
                             const float* __restrict__ W1, int n) {
    extern __shared__ float smem[];
    float* sW = smem;                    // [D_IN*H1] = 4096 floats (16 KB)
    float* sx = smem + D_IN * H1;        // [KT][257] transposed x tile

    int tid = threadIdx.x;
    for (int i = tid; i < D_IN * H1 / 4; i += G_THREADS)
        reinterpret_cast<float4*>(sW)[i] = reinterpret_cast<const float4*>(W1)[i];

    int row0 = blockIdx.x * G_THREADS;
    int row = row0 + tid;

    unsigned long long acc[8];   // f32x2 pairs: features (0,1)..(14,15)
#pragma unroll
    for (int j = 0; j < 8; j++) acc[j] = 0ull;

    for (int kt = 0; kt < D_IN; kt += KT) {
        __syncthreads();   // protect sx (prev-iter reads / W1 load on iter 0)
#pragma unroll
        for (int i = 0; i < 8; i++) {
            int idx = tid + i * G_THREADS;
            int r = idx >> 3, kv = idx & 7;
            if (row0 + r < n) {
                float4 v = __ldg(reinterpret_cast<const float4*>(
                    x + (size_t)(row0 + r) * D_IN + kt + kv * 4));
                int k = kv * 4;
                sx[(k + 0) * 257 + r] = v.x;   // bank (k+r)%32: conflict-free
                sx[(k + 1) * 257 + r] = v.y;
                sx[(k + 2) * 257 + r] = v.z;
                sx[(k + 3) * 257 + r] = v.w;
            }
        }
        __syncthreads();
#pragma unroll
        for (int kk = 0; kk < KT; kk++) {
            float xs = sx[kk * 257 + tid];
            unsigned long long x2;
            asm("mov.b64 %0, {%1, %1};" : "=l"(x2) : "f"(xs));
            const ulonglong2* wp =
                reinterpret_cast<const ulonglong2*>(sW + (kt + kk) * H1);
            ulonglong2 w01 = wp[0], w23 = wp[1], w45 = wp[2], w67 = wp[3];
            FMA2(acc[0], x2, w01.x); FMA2(acc[1], x2, w01.y);
            FMA2(acc[2], x2, w23.x); FMA2(acc[3], x2, w23.y);
            FMA2(acc[4], x2, w45.x); FMA2(acc[5], x2, w45.y);
            FMA2(acc[6], x2, w67.x); FMA2(acc[7], x2, w67.y);
        }
    }
    if (row < n) {
        ulonglong2* yr = reinterpret_cast<ulonglong2*>(g_y + (size_t)row * H1);
        yr[0] = make_ulonglong2(acc[0], acc[1]);
        yr[1] = make_ulonglong2(acc[2], acc[3]);
        yr[2] = make_ulonglong2(acc[4], acc[5]);
        yr[3] = make_ulonglong2(acc[6], acc[7]);
    }
}

// ---------------------------------------------------------------------------
// Edge pass, 4 edges per 4-lane group:
//   - 3 vector LDG.128 load r/c/v for 4 edges (shared by the group)
//   - per edge j: 4 lanes gather y[c_j] (LDG.128) and RED.v4 into a[r_j]
//   - s-RED: lane q handles edge 4g+q -> one warp-wide scalar RED per 32 edges
// LSU warp-ops per 32 edges: 3 + 4*2 + 1 = 12 (vs 24 in the per-edge scheme).
// ---------------------------------------------------------------------------
__global__ void edge_kernel(const int4* __restrict__ rows4,
                            const int4* __restrict__ cols4,
                            const float4* __restrict__ vals4, int quad_count) {
    int gid = blockIdx.x * blockDim.x + threadIdx.x;
    int q = gid & 3;             // lane within group = feature quarter
    int grp = gid >> 2;          // edge-quad index
    if (grp >= quad_count) return;

    int4   r4 = __ldg(rows4 + grp);
    int4   c4 = __ldg(cols4 + grp);
    float4 v4 = __ldg(vals4 + grp);

    // s accumulation: each lane takes one of the 4 edges
    int   cq = (q == 0) ? c4.x : (q == 1) ? c4.y : (q == 2) ? c4.z : c4.w;
    float vq = (q == 0) ? v4.x : (q == 1) ? v4.y : (q == 2) ? v4.z : v4.w;
    atomicAdd(&g_s[cq], vq);

    int   rr[4] = {r4.x, r4.y, r4.z, r4.w};
    int   cc[4] = {c4.x, c4.y, c4.z, c4.w};
    float vv[4] = {v4.x, v4.y, v4.z, v4.w};

    // Batch the 4 gathers first (independent -> MLP), then the 4 REDs.
    float4 yv[4];
#pragma unroll
    for (int j = 0; j < 4; j++)
        yv[j] = __ldg(reinterpret_cast<const float4*>(g_y + (size_t)cc[j] * H1) + q);
#pragma unroll
    for (int j = 0; j < 4; j++) {
        float* dst = g_a + (size_t)rr[j] * H1 + q * 4;
        asm volatile("red.global.add.v4.f32 [%0], {%1, %2, %3, %4};"
                     :: "l"(dst),
                        "f"(vv[j] * yv[j].x), "f"(vv[j] * yv[j].y),
                        "f"(vv[j] * yv[j].z), "f"(vv[j] * yv[j].w) : "memory");
    }
}

// ---------------------------------------------------------------------------
// t[f] = sum_i s[i] * relu(a[i][f]); self-cleans g_a/g_s; last block computes
// the final output and cleans g_t/g_ticket.
// ---------------------------------------------------------------------------
__global__ void reduce_final_kernel(int n,
                                    const float* __restrict__ W2,
                                    const float* __restrict__ w_out,
                                    const float* __restrict__ b_out,
                                    float* __restrict__ out) {
    __shared__ float4 red[256];
    __shared__ bool is_last;
    int tid = threadIdx.x;
    int g = tid & 3;  // feature group: covers features [4g, 4g+4)
    const float4 z4 = {0.f, 0.f, 0.f, 0.f};
    float4 acc = z4;
    int total = n * 4;
    int stride = gridDim.x * blockDim.x;
    for (int idx = blockIdx.x * blockDim.x + tid; idx < total; idx += stride) {
        int i = idx >> 2;
        float4* ap = reinterpret_cast<float4*>(g_a + (size_t)i * H1 + g * 4);
        float4 av = *ap;
        float s = 0.0f;
        if (g == 0) { s = g_s[i]; g_s[i] = 0.0f; }   // sole reader of g_s[i]
        s = __shfl_sync(0xffffffffu, s, (tid & 31) & ~3);
        *ap = z4;                                     // self-clean g_a
        acc.x += s * fmaxf(av.x, 0.f);
        acc.y += s * fmaxf(av.y, 0.f);
        acc.z += s * fmaxf(av.z, 0.f);
        acc.w += s * fmaxf(av.w, 0.f);
    }
    red[tid] = acc;
    __syncthreads();
#pragma unroll
    for (int off = 128; off >= 4; off >>= 1) {
        if (tid < off) {
            float4 o = red[tid + off];
            red[tid].x += o.x; red[tid].y += o.y; red[tid].z += o.z; red[tid].w += o.w;
        }
        __syncthreads();
    }
    if (tid < 4) {
        float4 r4 = red[tid];
        float* dst = g_t + tid * 4;
        asm volatile("red.global.add.v4.f32 [%0], {%1, %2, %3, %4};"
                     :: "l"(dst), "f"(r4.x), "f"(r4.y), "f"(r4.z), "f"(r4.w) : "memory");
    }
    __threadfence();
    if (tid == 0) {
        unsigned done = atomicAdd(&g_ticket, 1u);
        is_last = (done == gridDim.x - 1);
    }
    __syncthreads();
    if (is_last) {
        __threadfence();  // pair with producers' fences
        float z = 0.0f;
        if (tid < H2) {
#pragma unroll
            for (int fi = 0; fi < H1; fi++) z += g_t[fi] * W2[fi * H2 + tid];
        }
        __syncthreads();
        if (tid < H1) g_t[tid] = 0.0f;   // self-clean g_t
        if (tid == 0) g_ticket = 0u;     // self-clean ticket
        if (tid < H2) {
            float p = z * w_out[tid];
#pragma unroll
            for (int o = 16; o > 0; o >>= 1) p += __shfl_xor_sync(0xffffffffu, p, o);
            if (tid == 0) out[0] = 1.0f / (1.0f + expf(-(p + b_out[0])));
        }
    }
}

// ---------------------------------------------------------------------------
extern "C" void kernel_launch(void* const* d_in, const int* in_sizes, int n_in,
                              void* d_out, int out_size) {
    const float* x     = (const float*)d_in[0];
    const float* vals  = (const float*)d_in[1];
    const float* W1    = (const float*)d_in[2];
    const float* W2    = (const float*)d_in[3];
    const float* w_out = (const float*)d_in[4];
    const float* b_out = (const float*)d_in[5];
    const int*   rows  = (const int*)d_in[6];
    const int*   cols  = (const int*)d_in[7];

    int n = in_sizes[0] / D_IN;   // 100000
    int e = in_sizes[1];          // 3200000 (divisible by 4)

    int smem_bytes = (D_IN * H1 + KT * 257) * sizeof(float);  // 49280 B
    cudaFuncSetAttribute(gemm1_kernel,
                         cudaFuncAttributeMaxDynamicSharedMemorySize, smem_bytes);

    gemm1_kernel<<<(n + G_THREADS - 1) / G_THREADS, G_THREADS, smem_bytes>>>(x, W1, n);
    {
        int quads = e / 4;                       // 800000
        long long work = (long long)quads * 4;   // one thread per edge
        int blocks = (int)((work + 255) / 256);
        edge_kernel<<<blocks, 256>>>((const int4*)rows, (const int4*)cols,
                                     (const float4*)vals, quads);
    }
    reduce_final_kernel<<<1024, 256>>>(n, W2, w_out, b_out, (float*)d_out);
}

// round 11
// speedup vs baseline: 1.5873x; 1.0940x over previous
#include <cuda_runtime.h>
#include <cuda_bf16.h>
#include <math.h>

#define N_NODES_MAX 100000
#define D_IN        256
#define H1          16
#define H2          32
#define KPB         128      // k per block (k-split 2)
#define KT          16       // k staged per iteration
#define G_THREADS   256
#define G_ROWS      512      // rows per block (2 per thread)
#define SXS         20       // floats per tile row (80B, 16B-aligned, LDS.128 conflict-free)

#define FMA2(d, a, b) \
    asm("fma.rn.f32x2 %0, %1, %2, %0;" : "+l"(d) : "l"(a), "l"(b))

// Scratch (device globals — BSS zero-init; every call leaves them zeroed again,
// so the kernel is deterministic across graph replays).
__device__ __align__(256) float g_y[N_NODES_MAX * H1];   // x @ W1 (RED-accumulated, k-split)
__device__ __align__(256) float g_a[N_NODES_MAX * H1];   // spmm accumulator (pre-relu)
__device__ __align__(256) float g_s[N_NODES_MAX];        // s[j] = sum_{e: col==j} val[e]
__device__ __align__(256) float g_t[H1];                 // t = sum_i s[i]*relu(a[i])
__device__ unsigned g_ticket;                            // last-block ticket

// ---------------------------------------------------------------------------
// y = x @ W1   (N x 256) @ (256 x 16), k-split x2, 2 rows/thread.
// cp.async staging (no LDG->reg->STS double pass), row-major stride-20 tile
// (LDS.128 conflict-free), W broadcasts amortized over 64 rows/warp,
// fma.rn.f32x2 math, epilogue RED-accumulates into g_y.
// ---------------------------------------------------------------------------
__global__ void __launch_bounds__(G_THREADS, 4)
gemm1_kernel(const float* __restrict__ x, const float* __restrict__ W1, int n) {
    extern __shared__ float smem[];
    float* sW = smem;                  // [KPB*H1] = 2048 floats (8 KB)
    float* sx = smem + KPB * H1;       // [G_ROWS][SXS] = 10240 floats (40 KB)

    int tid = threadIdx.x;
    int tile = blockIdx.x >> 1;
    int kz = blockIdx.x & 1;
    int k0 = kz * KPB;
    int row0 = tile * G_ROWS;

    // W slice for this k half: 128 rows x 16 = 512 float4, 2 per thread
    reinterpret_cast<float4*>(sW)[tid] =
        reinterpret_cast<const float4*>(W1 + (size_t)k0 * H1)[tid];
    reinterpret_cast<float4*>(sW)[tid + G_THREADS] =
        reinterpret_cast<const float4*>(W1 + (size_t)k0 * H1)[tid + G_THREADS];

    unsigned long long accA[8], accB[8];   // f32x2 pairs: features (0,1)..(14,15)
#pragma unroll
    for (int j = 0; j < 8; j++) { accA[j] = 0ull; accB[j] = 0ull; }

    for (int kt = 0; kt < KPB; kt += KT) {
        __syncthreads();   // prev-iter compute done before overwriting sx
        // Stage: 512 rows x 4 chunks of 16B; 8 cp.async per thread.
        // idx -> (r = idx>>2, u = idx&3): 4 lanes = 64B contiguous in gmem.
#pragma unroll
        for (int i = 0; i < 8; i++) {
            int idx = tid + i * G_THREADS;
            int r = idx >> 2, u = idx & 3;
            if (row0 + r < n) {
                unsigned int dst = (unsigned int)__cvta_generic_to_shared(
                    sx + r * SXS + u * 4);
                const float* src = x + (size_t)(row0 + r) * D_IN + k0 + kt + u * 4;
                asm volatile("cp.async.cg.shared.global [%0], [%1], 16;"
                             :: "r"(dst), "l"(src));
            }
        }
        asm volatile("cp.async.commit_group;");
        asm volatile("cp.async.wait_group 0;");
        __syncthreads();
#pragma unroll
        for (int kk4 = 0; kk4 < KT / 4; kk4++) {
            float4 xa = *reinterpret_cast<const float4*>(sx + tid * SXS + kk4 * 4);
            float4 xb = *reinterpret_cast<const float4*>(
                sx + (tid + G_THREADS) * SXS + kk4 * 4);
#pragma unroll
            for (int j = 0; j < 4; j++) {
                float fa = (j == 0) ? xa.x : (j == 1) ? xa.y : (j == 2) ? xa.z : xa.w;
                float fb = (j == 0) ? xb.x : (j == 1) ? xb.y : (j == 2) ? xb.z : xb.w;
                unsigned long long xa2, xb2;
                asm("mov.b64 %0, {%1, %1};" : "=l"(xa2) : "f"(fa));
                asm("mov.b64 %0, {%1, %1};" : "=l"(xb2) : "f"(fb));
                const ulonglong2* wp = reinterpret_cast<const ulonglong2*>(
                    sW + (kt + kk4 * 4 + j) * H1);
                ulonglong2 w01 = wp[0], w23 = wp[1], w45 = wp[2], w67 = wp[3];
                FMA2(accA[0], xa2, w01.x); FMA2(accA[1], xa2, w01.y);
                FMA2(accA[2], xa2, w23.x); FMA2(accA[3], xa2, w23.y);
                FMA2(accA[4], xa2, w45.x); FMA2(accA[5], xa2, w45.y);
                FMA2(accA[6], xa2, w67.x); FMA2(accA[7], xa2, w67.y);
                FMA2(accB[0], xb2, w01.x); FMA2(accB[1], xb2, w01.y);
                FMA2(accB[2], xb2, w23.x); FMA2(accB[3], xb2, w23.y);
                FMA2(accB[4], xb2, w45.x); FMA2(accB[5], xb2, w45.y);
                FMA2(accB[6], xb2, w67.x); FMA2(accB[7], xb2, w67.y);
            }
        }
    }
    // Epilogue: RED partial y into g_y (2 k-split blocks accumulate)
#pragma unroll
    for (int half = 0; half < 2; half++) {
        int row = row0 + tid + half * G_THREADS;
        unsigned long long* acc = half ? accB : accA;
        if (row < n) {
#pragma unroll
            for (int j = 0; j < 4; j++) {
                float f0, f1, f2, f3;
                asm("mov.b64 {%0, %1}, %2;" : "=f"(f0), "=f"(f1) : "l"(acc[2 * j]));
                asm("mov.b64 {%0, %1}, %2;" : "=f"(f2), "=f"(f3) : "l"(acc[2 * j + 1]));
                float* dst = g_y + (size_t)row * H1 + j * 4;
                asm volatile("red.global.add.v4.f32 [%0], {%1, %2, %3, %4};"
                             :: "l"(dst), "f"(f0), "f"(f1), "f"(f2), "f"(f3) : "memory");
            }
        }
    }
}

// ---------------------------------------------------------------------------
// Edge pass, 4 edges per 4-lane group (R10 config — best known):
//   - 3 vector LDG.128 load r/c/v for 4 edges (shared by the group)
//   - per edge j: 4 lanes gather y[c_j] (LDG.128) and RED.v4 into a[r_j]
//   - s-RED: lane q handles edge 4g+q
// ---------------------------------------------------------------------------
__global__ void edge_kernel(const int4* __restrict__ rows4,
                            const int4* __restrict__ cols4,
                            const float4* __restrict__ vals4, int quad_count) {
    int gid = blockIdx.x * blockDim.x + threadIdx.x;
    int q = gid & 3;             // lane within group = feature quarter
    int grp = gid >> 2;          // edge-quad index
    if (grp >= quad_count) return;

    int4   r4 = __ldg(rows4 + grp);
    int4   c4 = __ldg(cols4 + grp);
    float4 v4 = __ldg(vals4 + grp);

    int   cq = (q == 0) ? c4.x : (q == 1) ? c4.y : (q == 2) ? c4.z : c4.w;
    float vq = (q == 0) ? v4.x : (q == 1) ? v4.y : (q == 2) ? v4.z : v4.w;
    atomicAdd(&g_s[cq], vq);

    int   rr[4] = {r4.x, r4.y, r4.z, r4.w};
    int   cc[4] = {c4.x, c4.y, c4.z, c4.w};
    float vv[4] = {v4.x, v4.y, v4.z, v4.w};

    float4 yv[4];
#pragma unroll
    for (int j = 0; j < 4; j++)
        yv[j] = __ldg(reinterpret_cast<const float4*>(g_y + (size_t)cc[j] * H1) + q);
#pragma unroll
    for (int j = 0; j < 4; j++) {
        float* dst = g_a + (size_t)rr[j] * H1 + q * 4;
        asm volatile("red.global.add.v4.f32 [%0], {%1, %2, %3, %4};"
                     :: "l"(dst),
                        "f"(vv[j] * yv[j].x), "f"(vv[j] * yv[j].y),
                        "f"(vv[j] * yv[j].z), "f"(vv[j] * yv[j].w) : "memory");
    }
}

// ---------------------------------------------------------------------------
// t[f] = sum_i s[i] * relu(a[i][f]); self-cleans g_a/g_s/g_y; last block
// computes the final output and cleans g_t/g_ticket.
// ---------------------------------------------------------------------------
__global__ void reduce_final_kernel(int n,
                                    const float* __restrict__ W2,
                                    const float* __restrict__ w_out,
                                    const float* __restrict__ b_out,
                                    float* __restrict__ out) {
    __shared__ float4 red[256];
    __shared__ bool is_last;
    int tid = threadIdx.x;
    int g = tid & 3;  // feature group: covers features [4g, 4g+4)
    const float4 z4 = {0.f, 0.f, 0.f, 0.f};
    float4 acc = z4;
    int total = n * 4;
    int stride = gridDim.x * blockDim.x;
    for (int idx = blockIdx.x * blockDim.x + tid; idx < total; idx += stride) {
        int i = idx >> 2;
        float4* ap = reinterpret_cast<float4*>(g_a + (size_t)i * H1 + g * 4);
        float4 av = *ap;
        float s = 0.0f;
        if (g == 0) { s = g_s[i]; g_s[i] = 0.0f; }   // sole reader of g_s[i]
        s = __shfl_sync(0xffffffffu, s, (tid & 31) & ~3);
        *ap = z4;                                     // self-clean g_a
        *reinterpret_cast<float4*>(g_y + (size_t)i * H1 + g * 4) = z4;  // clean g_y
        acc.x += s * fmaxf(av.x, 0.f);
        acc.y += s * fmaxf(av.y, 0.f);
        acc.z += s * fmaxf(av.z, 0.f);
        acc.w += s * fmaxf(av.w, 0.f);
    }
    red[tid] = acc;
    __syncthreads();
#pragma unroll
    for (int off = 128; off >= 4; off >>= 1) {
        if (tid < off) {
            float4 o = red[tid + off];
            red[tid].x += o.x; red[tid].y += o.y; red[tid].z += o.z; red[tid].w += o.w;
        }
        __syncthreads();
    }
    if (tid < 4) {
        float4 r4 = red[tid];
        float* dst = g_t + tid * 4;
        asm volatile("red.global.add.v4.f32 [%0], {%1, %2, %3, %4};"
                     :: "l"(dst), "f"(r4.x), "f"(r4.y), "f"(r4.z), "f"(r4.w) : "memory");
    }
    __threadfence();
    if (tid == 0) {
        unsigned done = atomicAdd(&g_ticket, 1u);
        is_last = (done == gridDim.x - 1);
    }
    __syncthreads();
    if (is_last) {
        __threadfence();  // pair with producers' fences
        float z = 0.0f;
        if (tid < H2) {
#pragma unroll
            for (int fi = 0; fi < H1; fi++) z += g_t[fi] * W2[fi * H2 + tid];
        }
        __syncthreads();
        if (tid < H1) g_t[tid] = 0.0f;   // self-clean g_t
        if (tid == 0) g_ticket = 0u;     // self-clean ticket
        if (tid < H2) {
            float p = z * w_out[tid];
#pragma unroll
            for (int o = 16; o > 0; o >>= 1) p += __shfl_xor_sync(0xffffffffu, p, o);
            if (tid == 0) out[0] = 1.0f / (1.0f + expf(-(p + b_out[0])));
        }
    }
}

// ---------------------------------------------------------------------------
extern "C" void kernel_launch(void* const* d_in, const int* in_sizes, int n_in,
                              void* d_out, int out_size) {
    const float* x     = (const float*)d_in[0];
    const float* vals  = (const float*)d_in[1];
    const float* W1    = (const float*)d_in[2];
    const float* W2    = (const float*)d_in[3];
    const float* w_out = (const float*)d_in[4];
    const float* b_out = (const float*)d_in[5];
    const int*   rows  = (const int*)d_in[6];
    const int*   cols  = (const int*)d_in[7];

    int n = in_sizes[0] / D_IN;   // 100000
    int e = in_sizes[1];          // 3200000 (divisible by 4)

    int smem_bytes = (KPB * H1 + G_ROWS * SXS) * sizeof(float);  // 49152 B
    cudaFuncSetAttribute(gemm1_kernel,
                         cudaFuncAttributeMaxDynamicSharedMemorySize, smem_bytes);

    int tiles = (n + G_ROWS - 1) / G_ROWS;   // 196
    gemm1_kernel<<<tiles * 2, G_THREADS, smem_bytes>>>(x, W1, n);
    {
        int quads = e / 4;                       // 800000
        long long work = (long long)quads * 4;
        int blocks = (int)((work + 255) / 256);
        edge_kernel<<<blocks, 256>>>((const int4*)rows, (const int4*)cols,
                                     (const float4*)vals, quads);
    }
    reduce_final_kernel<<<1024, 256>>>(n, W2, w_out, b_out, (float*)d_out);
}